// round 2
// baseline (speedup 1.0000x reference)
#include <cuda_runtime.h>

typedef unsigned long long ull;

namespace {
constexpr int H = 512;
constexpr int B = 64;
constexpr int T = 1000;
constexpr int COLS = 4;
constexpr int NWORK = H / COLS;      // 128 worker CTAs
constexpr int NCTA = NWORK + 1;      // +1 output CTA
constexpr int NT = 256;
constexpr int WSM_ULL = 2 * 3 * COLS * H;  // 12288 pair-duplicated weights
constexpr int RED_ULL = 384;
constexpr unsigned SMEM_BYTES = WSM_ULL * 8 + RED_ULL * 8 + 128;
}

__device__ float g_x[2][H][B];   // hidden state, k-major (batch contiguous)
__device__ float g_h0[H][B];     // layer-0 output
__device__ unsigned g_bar_count = 0;
__device__ unsigned g_bar_gen = 0;

__device__ __forceinline__ ull fma2(ull a, ull b, ull c) {
    ull d;
    asm("fma.rn.f32x2 %0, %1, %2, %3;" : "=l"(d) : "l"(a), "l"(b), "l"(c));
    return d;
}
__device__ __forceinline__ ull add2(ull a, ull b) {
    ull d;
    asm("add.rn.f32x2 %0, %1, %2;" : "=l"(d) : "l"(a), "l"(b));
    return d;
}
__device__ __forceinline__ ull pack2(float lo, float hi) {
    ull d;
    asm("mov.b64 %0, {%1, %2};" : "=l"(d) : "f"(lo), "f"(hi));
    return d;
}
__device__ __forceinline__ void unpack2(ull v, float& lo, float& hi) {
    asm("mov.b64 {%0, %1}, %2;" : "=f"(lo), "=f"(hi) : "l"(v));
}

__device__ __forceinline__ float sigm(float x) {
    return __fdividef(1.0f, 1.0f + __expf(-x));
}
__device__ __forceinline__ float tanh_(float x) {
    return __fmaf_rn(2.0f, sigm(x + x), -1.0f);
}

// Grid-wide barrier; 129 CTAs <= 148 SMs, all co-resident (1 CTA/SM).
// thread0's __threadfence() (gpu scope) emits CCTL.IVALL on sm_103a, which
// invalidates this SM's L1D, so post-barrier plain LDGs read fresh L2 data.
__device__ __forceinline__ void grid_barrier() {
    __syncthreads();
    if (threadIdx.x == 0) {
        __threadfence();
        unsigned gen = *(volatile unsigned*)&g_bar_gen;  // read BEFORE arriving
        if (atomicAdd(&g_bar_count, 1u) == NCTA - 1) {
            g_bar_count = 0;
            __threadfence();
            atomicExch(&g_bar_gen, gen + 1u);
        } else {
            while (*(volatile unsigned*)&g_bar_gen == gen) __nanosleep(64);
        }
    }
    __syncthreads();
}

__global__ __launch_bounds__(NT, 1) void fhn_kernel(
    const float* u0, const float* w0, const float* Kc,
    const float* W_in, const float* b_in,
    const float* W_ih0, const float* b_ih0, const float* b_hh0,
    const float* W_ih1, const float* b_ih1, const float* b_hh1,
    const float* W_u, const float* b_u, const float* W_w, const float* b_w,
    float* out)
{
    extern __shared__ ull smem[];
    ull* Wsm = smem;                 // [2][3][COLS][H] pair-duplicated f32x2
    ull* red = smem + WSM_ULL;       // cross-half reduction buffer
    float* bsm = (float*)(red + RED_ULL);  // [2][3][COLS] fused biases

    const int tid = threadIdx.x;
    const int cta = blockIdx.x;

    if (cta < NWORK) {
        // ---------------- worker CTA: 4 h-columns, both layers ----------------
        const int c0 = cta * COLS;
        const int gbase[3] = {0, 2 * H, 3 * H};  // i, g, o rows (f dead)

        for (int idx = tid; idx < WSM_ULL; idx += NT) {
            int k = idx & (H - 1);
            int r = idx >> 9;               // (l*3+g)*COLS + cc
            int l = r / 12, rem = r % 12;
            int g = rem >> 2, cc = rem & 3;
            const float* W = l ? W_ih1 : W_ih0;
            float v = W[(gbase[g] + c0 + cc) * H + k];
            Wsm[idx] = pack2(v, v);
        }
        if (tid < 24) {
            int r = tid;
            int l = r / 12, rem = r % 12;
            int g = rem >> 2, cc = rem & 3;
            int row = gbase[g] + c0 + cc;
            bsm[r] = l ? (b_ih1[row] + b_hh1[row]) : (b_ih0[row] + b_hh0[row]);
        }
        {   // x0 = [u0,w0,K] @ W_in.T + b_in  (this CTA's 4 k-rows)
            int c = c0 + (tid >> 6);
            int b = tid & 63;
            float v = u0[b] * W_in[c * 3 + 0] + w0[b] * W_in[c * 3 + 1]
                    + Kc[b] * W_in[c * 3 + 2] + b_in[c];
            g_x[0][c][b] = v;
        }
        grid_barrier();

        const int p = tid & 31;           // batch pair: rows 2p, 2p+1
        const int cc = (tid >> 5) & 3;    // column within CTA
        const int half = tid >> 7;        // k-half
        const int c = c0 + cc;
        const int k0 = half * (H / 2);

        for (int t = 0; t < T; ++t) {
            #pragma unroll
            for (int l = 0; l < 2; ++l) {
                const float* src = l ? &g_h0[0][0] : &g_x[t & 1][0][0];
                float* dst = l ? &g_x[(t + 1) & 1][0][0] : &g_h0[0][0];
                const ull* wi = Wsm + ((l * 3 + 0) * COLS + cc) * H;
                const ull* wg = Wsm + ((l * 3 + 1) * COLS + cc) * H;
                const ull* wo = Wsm + ((l * 3 + 2) * COLS + cc) * H;
                const ull* xp = (const ull*)src + p;  // (k, 2p) pair = xp[k*32]

                ull ai = 0, ag = 0, ao = 0;
                #pragma unroll 4
                for (int k = k0; k < k0 + H / 2; k += 2) {
                    ull x0v = xp[k * 32];
                    ull x1v = xp[(k + 1) * 32];
                    ulonglong2 wiv = *(const ulonglong2*)(wi + k);
                    ulonglong2 wgv = *(const ulonglong2*)(wg + k);
                    ulonglong2 wov = *(const ulonglong2*)(wo + k);
                    ai = fma2(x0v, wiv.x, ai);
                    ag = fma2(x0v, wgv.x, ag);
                    ao = fma2(x0v, wov.x, ao);
                    ai = fma2(x1v, wiv.y, ai);
                    ag = fma2(x1v, wgv.y, ag);
                    ao = fma2(x1v, wov.y, ao);
                }
                if (half) {
                    ull* r = red + (cc * 32 + p) * 3;
                    r[0] = ai; r[1] = ag; r[2] = ao;
                }
                __syncthreads();
                if (!half) {
                    const ull* r = red + (cc * 32 + p) * 3;
                    ai = add2(ai, r[0]);
                    ag = add2(ag, r[1]);
                    ao = add2(ao, r[2]);
                    float bi = bsm[(l * 3 + 0) * 4 + cc];
                    float bg = bsm[(l * 3 + 1) * 4 + cc];
                    float bo = bsm[(l * 3 + 2) * 4 + cc];
                    float i0, i1, gg0, gg1, o0, o1;
                    unpack2(ai, i0, i1);
                    unpack2(ag, gg0, gg1);
                    unpack2(ao, o0, o1);
                    i0 += bi; i1 += bi;
                    gg0 += bg; gg1 += bg;
                    o0 += bo; o1 += bo;
                    // h = sigmoid(o) * tanh(sigmoid(i) * tanh(g))   (f-gate dead)
                    float h0v = sigm(o0) * tanh_(sigm(i0) * tanh_(gg0));
                    float h1v = sigm(o1) * tanh_(sigm(i1) * tanh_(gg1));
                    *((ull*)dst + c * 32 + p) = pack2(h0v, h1v);
                }
                grid_barrier();
            }
        }
    } else {
        // ---------------- output CTA: u/w dots, one step behind ----------------
        for (int idx = tid; idx < 2 * H; idx += NT) {
            int o = idx >> 9, k = idx & (H - 1);
            float v = o ? W_w[k] : W_u[k];
            Wsm[idx] = pack2(v, v);
        }
        const float bias = ((tid >> 5) & 1) ? b_w[0] : b_u[0];
        grid_barrier();

        const int p = tid & 31;          // batch pair
        const int o = (tid >> 5) & 1;    // 0 -> u, 1 -> w
        const int q = tid >> 6;          // k quarter
        for (int t = 0; t <= T; ++t) {
            if (t > 0) {
                const float* src = &g_x[t & 1][0][0];  // = h1 of step t-1
                const ull* xp = (const ull*)src + p;
                const ull* wv = Wsm + o * H;
                ull acc = 0;
                const int kq = q * (H / 4);
                #pragma unroll 4
                for (int k = kq; k < kq + H / 4; ++k)
                    acc = fma2(xp[k * 32], wv[k], acc);
                if (q) red[(q - 1) * 64 + o * 32 + p] = acc;
                __syncthreads();
                if (!q) {
                    acc = add2(acc, red[o * 32 + p]);
                    acc = add2(acc, red[64 + o * 32 + p]);
                    acc = add2(acc, red[128 + o * 32 + p]);
                    float lo, hi;
                    unpack2(acc, lo, hi);
                    lo += bias; hi += bias;
                    const int tau = t - 1;
                    float* ob = out + o * (B * T);   // us then ws, each [B][T]
                    ob[(2 * p) * T + tau] = lo;
                    ob[(2 * p + 1) * T + tau] = hi;
                }
                __syncthreads();
            }
            if (t < T) { grid_barrier(); grid_barrier(); }
        }
    }
}

extern "C" void kernel_launch(void* const* d_in, const int* in_sizes, int n_in,
                              void* d_out, int out_size) {
    (void)in_sizes; (void)n_in; (void)out_size;
    static int smem_set = 0;
    if (!smem_set) {
        cudaFuncSetAttribute(fhn_kernel,
                             cudaFuncAttributeMaxDynamicSharedMemorySize,
                             (int)SMEM_BYTES);
        smem_set = 1;
    }
    fhn_kernel<<<NCTA, NT, SMEM_BYTES>>>(
        (const float*)d_in[0],   // u0
        (const float*)d_in[1],   // w0
        (const float*)d_in[2],   // K
        (const float*)d_in[3],   // W_in
        (const float*)d_in[4],   // b_in
        (const float*)d_in[5],   // W_ih0   (W_hh0 @6 unused)
        (const float*)d_in[7],   // b_ih0
        (const float*)d_in[8],   // b_hh0
        (const float*)d_in[9],   // W_ih1   (W_hh1 @10 unused)
        (const float*)d_in[11],  // b_ih1
        (const float*)d_in[12],  // b_hh1
        (const float*)d_in[13],  // W_u
        (const float*)d_in[14],  // b_u
        (const float*)d_in[15],  // W_w
        (const float*)d_in[16],  // b_w
        (float*)d_out);
}

// round 4
// speedup vs baseline: 1.3954x; 1.3954x over previous
#include <cuda_runtime.h>

typedef unsigned long long ull;
typedef unsigned int uint;

namespace {
constexpr int H = 512;
constexpr int B = 64;
constexpr int T = 1000;
constexpr int COLS = 4;
constexpr int NWORK = 128;           // worker CTAs (4 h-columns each)
constexpr int NCTA = NWORK + 1;      // + output CTA
constexpr int NT = 256;
constexpr int WSM_ULL = 2 * 3 * COLS * H;   // 12288 ull = 96KB pair-dup weights
constexpr int XSM_ULL = H * (B / 2);        // 16384 ull = 128KB staged x
constexpr int RED_ULL = WSM_ULL + XSM_ULL - 384;  // red aliases x tail (k 500-511)
constexpr int SPARE_ULL = WSM_ULL + XSM_ULL;      // 3KB spare: mbars, flags
constexpr unsigned SMEM_BYTES = (WSM_ULL + XSM_ULL) * 8 + 3072;  // 232448 = max
}

__device__ float g_x[2][H][B];   // hidden state, k-major (batch contiguous)
__device__ float g_h0[H][B];     // layer-0 output
__device__ uint g_count = 0;
__device__ uint g_gen = 0;
__device__ uint g_pub = 0;

__device__ __forceinline__ ull fma2(ull a, ull b, ull c) {
    ull d; asm("fma.rn.f32x2 %0, %1, %2, %3;" : "=l"(d) : "l"(a), "l"(b), "l"(c));
    return d;
}
__device__ __forceinline__ ull add2(ull a, ull b) {
    ull d; asm("add.rn.f32x2 %0, %1, %2;" : "=l"(d) : "l"(a), "l"(b));
    return d;
}
__device__ __forceinline__ ull pack2(float lo, float hi) {
    ull d; asm("mov.b64 %0, {%1, %2};" : "=l"(d) : "f"(lo), "f"(hi));
    return d;
}
__device__ __forceinline__ void unpack2(ull v, float& lo, float& hi) {
    asm("mov.b64 {%0, %1}, %2;" : "=f"(lo), "=f"(hi) : "l"(v));
}
__device__ __forceinline__ float sigm(float x) {
    return __fdividef(1.0f, 1.0f + __expf(-x));
}
__device__ __forceinline__ float tanh_(float x) {
    return __fmaf_rn(2.0f, sigm(x + x), -1.0f);
}

// Fence-free grid barrier (no CCTL.IVALL). 129 CTAs, all co-resident.
// Release-atomic arrive orders prior STG; acquire-load spin orders later loads.
// High 16 bits of the arrive increment carry a per-CTA "changed" flag; the
// total is published and broadcast back to every thread via smem.
__device__ __forceinline__ uint grid_barrier(uint* sflag, uint* spub, int use_flag) {
    __syncthreads();
    if (threadIdx.x == 0) {
        uint changed = use_flag ? *sflag : 0u;
        uint snap, old, tot;
        asm volatile("ld.acquire.gpu.u32 %0, [%1];" : "=r"(snap) : "l"(&g_gen) : "memory");
        asm volatile("atom.add.release.gpu.u32 %0, [%1], %2;"
                     : "=r"(old) : "l"(&g_count), "r"(1u + (changed << 16)) : "memory");
        if ((old & 0xFFFFu) == NCTA - 1) {
            tot = (old >> 16) + changed;
            asm volatile("st.relaxed.gpu.u32 [%0], %1;" :: "l"(&g_pub), "r"(tot) : "memory");
            asm volatile("st.relaxed.gpu.u32 [%0], %1;" :: "l"(&g_count), "r"(0u) : "memory");
            asm volatile("st.release.gpu.u32 [%0], %1;" :: "l"(&g_gen), "r"(snap + 1u) : "memory");
        } else {
            uint g;
            do {
                asm volatile("ld.acquire.gpu.u32 %0, [%1];" : "=r"(g) : "l"(&g_gen) : "memory");
            } while (g == snap);
            asm volatile("ld.relaxed.gpu.u32 %0, [%1];" : "=r"(tot) : "l"(&g_pub) : "memory");
        }
        *spub = tot;
        *sflag = 0u;
    }
    __syncthreads();
    return *spub;
}

__device__ __forceinline__ void mbar_init(uint mbar, uint cnt) {
    asm volatile("mbarrier.init.shared.b64 [%0], %1;" :: "r"(mbar), "r"(cnt) : "memory");
}
__device__ __forceinline__ void mbar_expect_tx(uint mbar, uint tx) {
    asm volatile("mbarrier.arrive.expect_tx.shared.b64 _, [%0], %1;"
                 :: "r"(mbar), "r"(tx) : "memory");
}
__device__ __forceinline__ void bulk_g2s(uint dst_smem, const void* src, uint bytes, uint mbar) {
    asm volatile("cp.async.bulk.shared::cta.global.mbarrier::complete_tx::bytes "
                 "[%0], [%1], %2, [%3];"
                 :: "r"(dst_smem), "l"(src), "r"(bytes), "r"(mbar) : "memory");
}
__device__ __forceinline__ void mbar_wait(uint mbar, uint parity) {
    asm volatile(
        "{\n\t.reg .pred P;\n\t"
        "LW%=: mbarrier.try_wait.parity.shared.b64 P, [%0], %1, 0x989680;\n\t"
        "@P bra LD%=;\n\t"
        "bra LW%=;\n\t"
        "LD%=: }\n\t" :: "r"(mbar), "r"(parity) : "memory");
}
__device__ __forceinline__ uint smem_u32(const void* p) {
    uint a;
    asm("{ .reg .u64 t; cvta.to.shared.u64 t, %1; cvt.u32.u64 %0, t; }" : "=r"(a) : "l"(p));
    return a;
}

__global__ __launch_bounds__(NT, 1) void fhn_kernel(
    const float* u0, const float* w0, const float* Kc,
    const float* W_in, const float* b_in,
    const float* W_ih0, const float* b_ih0, const float* b_hh0,
    const float* W_ih1, const float* b_ih1, const float* b_hh1,
    const float* W_u, const float* b_u, const float* W_w, const float* b_w,
    float* out)
{
    extern __shared__ ull smem[];
    ull* Wsm = smem;                  // worker: pair-dup weights; out-CTA: W_u/W_w
    ull* Xsm = smem + WSM_ULL;        // worker: staged x [k][pair]
    ull* red = smem + RED_ULL;        // worker: aliases Xsm tail (guarded by syncs)
    ull* mb = smem + SPARE_ULL;       // mb[0], mb[1]
    uint* sflag = (uint*)(smem + SPARE_ULL + 2);
    uint* spub = sflag + 1;

    const int tid = threadIdx.x;
    const int cta = blockIdx.x;

    if (cta < NWORK) {
        // ======================= worker CTA =======================
        const int c0 = cta * COLS;
        const int gbase[3] = {0, 2 * H, 3 * H};  // i, g, o gate rows (f dead)

        for (int idx = tid; idx < WSM_ULL; idx += NT) {
            int k = idx & (H - 1);
            int r = idx >> 9;               // (l*3+g)*COLS + cc
            int l = r / 12, rem = r % 12;
            int g = rem >> 2, cc2 = rem & 3;
            const float* W = l ? W_ih1 : W_ih0;
            float v = W[(gbase[g] + c0 + cc2) * H + k];
            Wsm[idx] = pack2(v, v);
        }
        if (tid == 0) {
            mbar_init(smem_u32(&mb[0]), 1);
            mbar_init(smem_u32(&mb[1]), 1);
            asm volatile("fence.proxy.async.shared::cta;" ::: "memory");
            *sflag = 0u;
        }
        {   // x0 = [u0,w0,K] @ W_in.T + b_in
            int c = c0 + (tid >> 6);
            int b = tid & 63;
            float v = u0[b] * W_in[c * 3 + 0] + w0[b] * W_in[c * 3 + 1]
                    + Kc[b] * W_in[c * 3 + 2] + b_in[c];
            g_x[0][c][b] = v;
        }

        const int p = tid & 31;           // batch pair
        const int cc = (tid >> 5) & 3;    // column within CTA
        const int half = tid >> 7;        // k-half (warp-granular)
        const int c = c0 + cc;
        const int k0 = half * (H / 2);

        // fused biases in registers (only half-0 threads use them)
        float bi_[2], bg_[2], bo_[2];
        #pragma unroll
        for (int l = 0; l < 2; ++l) {
            const float* bih = l ? b_ih1 : b_ih0;
            const float* bhh = l ? b_hh1 : b_hh0;
            bi_[l] = bih[c] + bhh[c];
            bg_[l] = bih[2 * H + c] + bhh[2 * H + c];
            bo_[l] = bih[3 * H + c] + bhh[3 * H + c];
        }

        grid_barrier(sflag, spub, 0);

        const uint mb0 = smem_u32(&mb[0]);
        const uint mb1 = smem_u32(&mb[1]);
        const uint xsm0 = smem_u32(Xsm);
        int ph = 0;

        #pragma unroll 1
        for (int t = 0; t < T; ++t) {
            bool stop = false;
            #pragma unroll
            for (int l = 0; l < 2; ++l) {
                const ull* srcg = l ? (const ull*)&g_h0[0][0]
                                    : (const ull*)&g_x[t & 1][0][0];
                if (tid == 0) {
                    mbar_expect_tx(mb0, 65536);
                    bulk_g2s(xsm0, srcg, 65536, mb0);
                    mbar_expect_tx(mb1, 65536);
                    bulk_g2s(xsm0 + 65536, srcg + 8192, 65536, mb1);
                }
                mbar_wait(half ? mb1 : mb0, (uint)(ph & 1));
                ph++;

                ull oldx = 0;
                if (l == 1 && !half)
                    oldx = __ldcg((const ull*)&g_x[t & 1][0][0] + c * 32 + p);

                const ull* wi = Wsm + ((l * 3 + 0) * COLS + cc) * H;
                const ull* wg = Wsm + ((l * 3 + 1) * COLS + cc) * H;
                const ull* wo = Wsm + ((l * 3 + 2) * COLS + cc) * H;
                const ull* xp = Xsm + p;

                ull ai = 0, ag = 0, ao = 0;
                #pragma unroll 4
                for (int k = k0; k < k0 + H / 2; k += 2) {
                    ull x0v = xp[k * 32];
                    ull x1v = xp[k * 32 + 32];
                    ulonglong2 wiv = *(const ulonglong2*)(wi + k);
                    ulonglong2 wgv = *(const ulonglong2*)(wg + k);
                    ulonglong2 wov = *(const ulonglong2*)(wo + k);
                    ai = fma2(x0v, wiv.x, ai);
                    ag = fma2(x0v, wgv.x, ag);
                    ao = fma2(x0v, wov.x, ao);
                    ai = fma2(x1v, wiv.y, ai);
                    ag = fma2(x1v, wgv.y, ag);
                    ao = fma2(x1v, wov.y, ao);
                }
                __syncthreads();   // all Xsm reads done (red aliases Xsm tail)
                if (half) {
                    ull* r = red + (cc * 32 + p) * 3;
                    r[0] = ai; r[1] = ag; r[2] = ao;
                }
                __syncthreads();
                if (!half) {
                    const ull* r = red + (cc * 32 + p) * 3;
                    ai = add2(ai, r[0]);
                    ag = add2(ag, r[1]);
                    ao = add2(ao, r[2]);
                    float i0, i1, gg0, gg1, o0, o1;
                    unpack2(ai, i0, i1);
                    unpack2(ag, gg0, gg1);
                    unpack2(ao, o0, o1);
                    i0 += bi_[l]; i1 += bi_[l];
                    gg0 += bg_[l]; gg1 += bg_[l];
                    o0 += bo_[l]; o1 += bo_[l];
                    float h0v = sigm(o0) * tanh_(sigm(i0) * tanh_(gg0));
                    float h1v = sigm(o1) * tanh_(sigm(i1) * tanh_(gg1));
                    ull hv = pack2(h0v, h1v);
                    ull* dst = l ? (ull*)&g_x[(t + 1) & 1][0][0] : (ull*)&g_h0[0][0];
                    dst[c * 32 + p] = hv;
                    if (l == 1 && hv != oldx) *sflag = 1u;
                }
                uint tot = grid_barrier(sflag, spub, l);
                if (l == 1 && tot == 0) stop = true;
            }
            if (stop) break;   // bitwise fixed point: all later steps identical
        }
    } else {
        // ======================= output CTA =======================
        // Computes u/w for step t right after step t's barriers (overlapped
        // with the workers' step t+1). On convergence, fills the tail.
        for (int idx = tid; idx < 2 * H; idx += NT) {
            int o = idx >> 9, k = idx & (H - 1);
            float v = o ? W_w[k] : W_u[k];
            Wsm[idx] = pack2(v, v);
        }
        if (tid == 0) *sflag = 0u;
        const float bias = ((tid >> 5) & 1) ? b_w[0] : b_u[0];
        ull* red2 = smem + 2 * H;

        grid_barrier(sflag, spub, 0);

        const int p = tid & 31;          // batch pair
        const int o = (tid >> 5) & 1;    // 0 -> u, 1 -> w
        const int q = tid >> 6;          // k quarter
        const ull* wv = Wsm + o * H;

        #pragma unroll 1
        for (int t = 0; t < T; ++t) {
            grid_barrier(sflag, spub, 0);              // layer-0 done
            uint tot = grid_barrier(sflag, spub, 0);   // layer-1 done
            // h1_t = g_x[(t+1)&1]; fresh via .cg (L2) loads
            const ull* xp = (const ull*)&g_x[(t + 1) & 1][0][0] + p;
            ull acc = 0;
            const int kq = q * (H / 4);
            #pragma unroll 8
            for (int k = kq; k < kq + H / 4; ++k)
                acc = fma2(__ldcg(xp + k * 32), wv[k], acc);
            if (q) red2[(q - 1) * 64 + o * 32 + p] = acc;
            __syncthreads();
            if (!q) {
                acc = add2(acc, red2[o * 32 + p]);
                acc = add2(acc, red2[64 + o * 32 + p]);
                acc = add2(acc, red2[128 + o * 32 + p]);
                float lo, hi;
                unpack2(acc, lo, hi);
                lo += bias; hi += bias;
                float* ob = out + o * (B * T);   // us then ws, each [B][T]
                ob[(2 * p) * T + t] = lo;
                ob[(2 * p + 1) * T + t] = hi;
                if (tot == 0) {
                    for (int tau = t + 1; tau < T; ++tau) {
                        ob[(2 * p) * T + tau] = lo;
                        ob[(2 * p + 1) * T + tau] = hi;
                    }
                }
            }
            __syncthreads();
            if (tot == 0) break;
        }
    }
}

extern "C" void kernel_launch(void* const* d_in, const int* in_sizes, int n_in,
                              void* d_out, int out_size) {
    (void)in_sizes; (void)n_in; (void)out_size;
    cudaFuncSetAttribute(fhn_kernel, cudaFuncAttributeMaxDynamicSharedMemorySize,
                         (int)SMEM_BYTES);
    fhn_kernel<<<NCTA, NT, SMEM_BYTES>>>(
        (const float*)d_in[0],   // u0
        (const float*)d_in[1],   // w0
        (const float*)d_in[2],   // K
        (const float*)d_in[3],   // W_in
        (const float*)d_in[4],   // b_in
        (const float*)d_in[5],   // W_ih0   (W_hh0 @6 unused)
        (const float*)d_in[7],   // b_ih0
        (const float*)d_in[8],   // b_hh0
        (const float*)d_in[9],   // W_ih1   (W_hh1 @10 unused)
        (const float*)d_in[11],  // b_ih1
        (const float*)d_in[12],  // b_hh1
        (const float*)d_in[13],  // W_u
        (const float*)d_in[14],  // b_u
        (const float*)d_in[15],  // W_w
        (const float*)d_in[16],  // b_w
        (float*)d_out);
}

// round 6
// speedup vs baseline: 1.5717x; 1.1264x over previous
#include <cuda_runtime.h>

typedef unsigned long long ull;
typedef unsigned int uint;

namespace {
constexpr int H = 512;
constexpr int B = 64;
constexpr int T = 1000;
constexpr int COLS = 4;
constexpr int NWORK = 128;
constexpr int NCTA = NWORK + 1;
constexpr int NT = 256;
constexpr int WSM_ULL = 2 * 3 * COLS * H;   // 12288 ull = 96KB pair-dup weights
constexpr int XSM_ULL = H * (B / 2);        // 16384 ull = 128KB staged x
constexpr int RED_OFF = XSM_ULL - 3072;     // red aliases Xsm tail (k 416..511)
constexpr int SPARE_ULL = WSM_ULL + XSM_ULL;
constexpr unsigned SMEM_BYTES = SPARE_ULL * 8 + 512;   // 229888 <= 232448 max
}

__device__ float g_x[2][H][B];     // hidden state, k-major (batch contiguous)
__device__ float g_h0[H][B];       // layer-0 output
__device__ uint g_flags[NCTA];     // [0..127] workers: phase|sticky<<16; [128] output: phase
__device__ uint g_tconv = 0x7FFFFFFFu;  // step at which bitwise convergence detected
__device__ uint g_count = 0;       // final barrier
__device__ uint g_gen = 0;

__device__ __forceinline__ ull fma2(ull a, ull b, ull c) {
    ull d; asm("fma.rn.f32x2 %0, %1, %2, %3;" : "=l"(d) : "l"(a), "l"(b), "l"(c));
    return d;
}
__device__ __forceinline__ ull add2(ull a, ull b) {
    ull d; asm("add.rn.f32x2 %0, %1, %2;" : "=l"(d) : "l"(a), "l"(b));
    return d;
}
__device__ __forceinline__ ull pack2(float lo, float hi) {
    ull d; asm("mov.b64 %0, {%1, %2};" : "=l"(d) : "f"(lo), "f"(hi));
    return d;
}
__device__ __forceinline__ void unpack2(ull v, float& lo, float& hi) {
    asm("mov.b64 {%0, %1}, %2;" : "=f"(lo), "=f"(hi) : "l"(v));
}
__device__ __forceinline__ float sigm(float x) {
    return __fdividef(1.0f, 1.0f + __expf(-x));
}
__device__ __forceinline__ float tanh_(float x) {
    return __fmaf_rn(2.0f, sigm(x + x), -1.0f);
}

// Distributed flag barrier: warp 0 polls all 128 worker flags (+ output flag,
// lane 0). Distinct addresses -> no atomic serialization. *spub gets the OR of
// worker sticky bits. Frozen flags (0xFFFF) pass any phase with sticky 0.
__device__ __forceinline__ void poll_flags(uint ph, uint* spub) {
    if (threadIdx.x < 32) {
        uint any = 0;
        #pragma unroll
        for (int j = 0; j < 4; ++j) {
            const uint* a = &g_flags[threadIdx.x + j * 32];
            uint f;
            do {
                asm volatile("ld.acquire.gpu.u32 %0, [%1];" : "=r"(f) : "l"(a) : "memory");
            } while ((f & 0xFFFFu) < ph);
            any |= (f >> 16);
        }
        if (threadIdx.x == 0) {
            const uint* a = &g_flags[NWORK];
            uint f;
            do {
                asm volatile("ld.acquire.gpu.u32 %0, [%1];" : "=r"(f) : "l"(a) : "memory");
            } while (f < ph);
        }
        uint r = __any_sync(0xFFFFFFFFu, any != 0u);
        if (threadIdx.x == 0) *spub = r;
    }
}

__device__ __forceinline__ void publish(uint* addr, uint v) {
    asm volatile("st.release.gpu.u32 [%0], %1;" :: "l"(addr), "r"(v) : "memory");
}

__device__ __forceinline__ void final_barrier() {
    __syncthreads();
    if (threadIdx.x == 0) {
        uint snap, old;
        asm volatile("ld.acquire.gpu.u32 %0, [%1];" : "=r"(snap) : "l"(&g_gen) : "memory");
        asm volatile("atom.add.release.gpu.u32 %0, [%1], %2;"
                     : "=r"(old) : "l"(&g_count), "r"(1u) : "memory");
        if (old == NCTA - 1) {
            asm volatile("st.relaxed.gpu.u32 [%0], %1;" :: "l"(&g_count), "r"(0u) : "memory");
            asm volatile("st.release.gpu.u32 [%0], %1;" :: "l"(&g_gen), "r"(snap + 1u) : "memory");
        } else {
            uint g;
            do {
                asm volatile("ld.acquire.gpu.u32 %0, [%1];" : "=r"(g) : "l"(&g_gen) : "memory");
            } while (g == snap);
        }
    }
    __syncthreads();
}

__device__ __forceinline__ void mbar_init(uint mbar, uint cnt) {
    asm volatile("mbarrier.init.shared.b64 [%0], %1;" :: "r"(mbar), "r"(cnt) : "memory");
}
__device__ __forceinline__ void mbar_expect_tx(uint mbar, uint tx) {
    asm volatile("mbarrier.arrive.expect_tx.shared.b64 _, [%0], %1;"
                 :: "r"(mbar), "r"(tx) : "memory");
}
__device__ __forceinline__ void bulk_g2s(uint dst, const void* src, uint bytes, uint mbar) {
    asm volatile("cp.async.bulk.shared::cta.global.mbarrier::complete_tx::bytes "
                 "[%0], [%1], %2, [%3];" :: "r"(dst), "l"(src), "r"(bytes), "r"(mbar)
                 : "memory");
}
__device__ __forceinline__ void mbar_wait(uint mbar, uint parity) {
    asm volatile(
        "{\n\t.reg .pred P;\n\t"
        "LW%=: mbarrier.try_wait.parity.shared.b64 P, [%0], %1, 0x989680;\n\t"
        "@P bra LD%=;\n\t"
        "bra LW%=;\n\t"
        "LD%=: }\n\t" :: "r"(mbar), "r"(parity) : "memory");
}
__device__ __forceinline__ uint smem_u32(const void* p) {
    uint a;
    asm("{ .reg .u64 t; cvta.to.shared.u64 t, %1; cvt.u32.u64 %0, t; }" : "=r"(a) : "l"(p));
    return a;
}

__global__ __launch_bounds__(NT, 1) void fhn_kernel(
    const float* u0, const float* w0, const float* Kc,
    const float* W_in, const float* b_in,
    const float* W_ih0, const float* b_ih0, const float* b_hh0,
    const float* W_ih1, const float* b_ih1, const float* b_hh1,
    const float* W_u, const float* b_u, const float* W_w, const float* b_w,
    float* out)
{
    extern __shared__ ull smem[];
    ull* Wsm = smem;                      // [row r=l*12+g*4+c][k] pair-dup
    ull* Xsm = smem + WSM_ULL;            // staged x, [k][pair]
    ull* red = Xsm + RED_OFF;             // reduction, aliases Xsm tail
    ull* mb = smem + SPARE_ULL;           // mb[0..3]
    uint* sflag = (uint*)(smem + SPARE_ULL + 4);
    uint* spub = sflag + 1;
    uint* stcv = sflag + 2;
    float* bsm = (float*)(sflag + 4);     // 24 fused biases

    const int tid = threadIdx.x;
    const int cta = blockIdx.x;

    if (cta < NWORK) {
        // ========================= worker CTA =========================
        const int c0 = cta * COLS;
        const int gbase[3] = {0, 2 * H, 3 * H};  // i, g, o rows (f-gate dead)

        for (int idx = tid; idx < WSM_ULL; idx += NT) {
            int k = idx & (H - 1);
            int r = idx >> 9;                 // r = l*12 + g*4 + c
            int l = r / 12, rem = r % 12;
            int g = rem >> 2, c = rem & 3;
            const float* W = l ? W_ih1 : W_ih0;
            float v = W[(gbase[g] + c0 + c) * H + k];
            Wsm[idx] = pack2(v, v);
        }
        if (tid < 24) {
            int l = tid / 12, rem = tid % 12;
            int g = rem >> 2, c = rem & 3;
            int row = gbase[g] + c0 + c;
            bsm[tid] = l ? (b_ih1[row] + b_hh1[row]) : (b_ih0[row] + b_hh0[row]);
        }
        if (tid == 0) {
            #pragma unroll
            for (int c = 0; c < 4; ++c) mbar_init(smem_u32(&mb[c]), 1);
            asm volatile("fence.proxy.async;" ::: "memory");
            *sflag = 0u;
        }
        {   // x0 = [u0,w0,K] @ W_in.T + b_in
            int c = c0 + (tid >> 6);
            int b = tid & 63;
            float v = u0[b] * W_in[c * 3 + 0] + w0[b] * W_in[c * 3 + 1]
                    + Kc[b] * W_in[c * 3 + 2] + b_in[c];
            g_x[0][c][b] = v;
        }

        uint sticky = 1u;
        __syncthreads();
        if (tid == 0) publish(&g_flags[cta], 1u | (sticky << 16));
        poll_flags(1u, spub);
        __syncthreads();

        const int p = tid & 31;     // batch pair (lane)
        const int e = tid >> 5;     // k-eighth (warp)
        const int k0 = e * 64;
        uint mbw = smem_u32(&mb[e >> 1]);
        const uint xsm0 = smem_u32(Xsm);

        int lyr = 0;
        int tdet = -1;
        bool done = false;
        #pragma unroll 1
        for (int t = 0; t < T && !done; ++t) {
            #pragma unroll
            for (int l = 0; l < 2; ++l) {
                const char* srcg = l ? (const char*)&g_h0[0][0]
                                     : (const char*)&g_x[t & 1][0][0];
                if (tid == 0) {
                    #pragma unroll
                    for (int c = 0; c < 4; ++c) {
                        uint m = smem_u32(&mb[c]);
                        mbar_expect_tx(m, 32768);
                        bulk_g2s(xsm0 + c * 32768, srcg + c * 32768, 32768, m);
                    }
                }
                ull oldv = 0;
                if (l == 1 && tid < 128)   // change detection, latency hidden
                    oldv = __ldcg((const ull*)&g_x[t & 1][0][0] + (c0 + (tid >> 5)) * 32 + p);

                mbar_wait(mbw, (uint)(lyr & 1));

                ull acc[12];
                #pragma unroll
                for (int j = 0; j < 12; ++j) acc[j] = 0;
                const ull* xp = Xsm + p;
                const ull* wb = Wsm + l * 12 * H;
                #pragma unroll 2
                for (int k = k0; k < k0 + 64; k += 2) {
                    ull x0v = xp[k * 32];
                    ull x1v = xp[k * 32 + 32];
                    ull wa[12], wc[12];
                    #pragma unroll
                    for (int j = 0; j < 12; ++j) {
                        ulonglong2 wv = *(const ulonglong2*)(wb + j * H + k);
                        wa[j] = wv.x; wc[j] = wv.y;
                    }
                    #pragma unroll
                    for (int j = 0; j < 12; ++j) acc[j] = fma2(x0v, wa[j], acc[j]);
                    #pragma unroll
                    for (int j = 0; j < 12; ++j) acc[j] = fma2(x1v, wc[j], acc[j]);
                }
                __syncthreads();   // all Xsm reads done; red may alias tail
                if (e >= 4) {
                    #pragma unroll
                    for (int j = 0; j < 12; ++j) red[j * 128 + (e - 4) * 32 + p] = acc[j];
                }
                __syncthreads();
                if (e < 4) {
                    #pragma unroll
                    for (int j = 0; j < 12; ++j) acc[j] = add2(acc[j], red[j * 128 + e * 32 + p]);
                    if (e >= 2) {
                        #pragma unroll
                        for (int j = 0; j < 12; ++j) red[1536 + j * 64 + (e - 2) * 32 + p] = acc[j];
                    }
                }
                __syncthreads();
                if (e < 2) {
                    #pragma unroll
                    for (int j = 0; j < 12; ++j) {
                        acc[j] = add2(acc[j], red[1536 + j * 64 + e * 32 + p]);
                        red[2304 + e * 384 + j * 32 + p] = acc[j];
                    }
                }
                __syncthreads();
                if (tid < 128) {
                    int c = tid >> 5;           // one c per warp (per SMSP)
                    ull s[3];
                    #pragma unroll
                    for (int g = 0; g < 3; ++g)   // j = g*4+c (FIXED)
                        s[g] = add2(red[2304 + (g * 4 + c) * 32 + p],
                                    red[2304 + 384 + (g * 4 + c) * 32 + p]);
                    float iv0, iv1, gv0, gv1, ov0, ov1;
                    unpack2(s[0], iv0, iv1);
                    unpack2(s[1], gv0, gv1);
                    unpack2(s[2], ov0, ov1);
                    float bi = bsm[l * 12 + 0 * 4 + c];
                    float bg = bsm[l * 12 + 1 * 4 + c];
                    float bo = bsm[l * 12 + 2 * 4 + c];
                    iv0 += bi; iv1 += bi;
                    gv0 += bg; gv1 += bg;
                    ov0 += bo; ov1 += bo;
                    float h0v = sigm(ov0) * tanh_(sigm(iv0) * tanh_(gv0));
                    float h1v = sigm(ov1) * tanh_(sigm(iv1) * tanh_(gv1));
                    ull hv = pack2(h0v, h1v);
                    ull* dst = l ? (ull*)&g_x[(t + 1) & 1][0][0] : (ull*)&g_h0[0][0];
                    dst[(c0 + c) * 32 + p] = hv;
                    if (l == 1 && hv != oldv) *sflag = 1u;
                }
                uint ph = (uint)(lyr + 2);
                __syncthreads();
                if (tid == 0) {
                    if (l == 1) { sticky = *sflag; *sflag = 0u; }
                    publish(&g_flags[cta], ph | (sticky << 16));
                }
                poll_flags(ph, spub);
                __syncthreads();
                if (l == 1 && *spub == 0u) { done = true; tdet = t; }
                lyr++;
            }
        }
        if (done && tid == 0) {
            asm volatile("st.relaxed.gpu.u32 [%0], %1;"
                         :: "l"(&g_tconv), "r"((uint)tdet) : "memory");
            publish(&g_flags[cta], 0xFFFFu);   // freeze: passes all phases
        }
    } else {
        // ========================= output CTA =========================
        for (int idx = tid; idx < 2 * H; idx += NT) {
            int o = idx >> 9, k = idx & (H - 1);
            float v = o ? W_w[k] : W_u[k];
            Wsm[idx] = pack2(v, v);
        }
        const float bias = ((tid >> 5) & 1) ? b_w[0] : b_u[0];
        ull* red2 = smem + 2 * H;
        __syncthreads();
        if (tid == 0) publish(&g_flags[NWORK], 5u);   // allow workers thru ph<=5

        const int p = tid & 31;          // batch pair
        const int o = (tid >> 5) & 1;    // 0 -> u, 1 -> w
        const int q = tid >> 6;          // k quarter
        const ull* wv = Wsm + o * H;

        #pragma unroll 1
        for (int t = 0; t < T; ++t) {
            uint ph = 3u + 2u * (uint)t;     // layer-1 phase of step t
            poll_flags(ph, spub);
            if (tid == 0) {
                uint tc;
                asm volatile("ld.relaxed.gpu.u32 %0, [%1];" : "=r"(tc) : "l"(&g_tconv) : "memory");
                *stcv = tc;
            }
            __syncthreads();
            bool fin = ((uint)(t + 1) >= *stcv) || (t == T - 1);
            const ull* xp = (const ull*)&g_x[(t + 1) & 1][0][0] + p;  // h1_t
            ull acc = 0;
            const int kq = q * (H / 4);
            #pragma unroll 8
            for (int k = kq; k < kq + H / 4; ++k)
                acc = fma2(__ldcg(xp + k * 32), wv[k], acc);
            if (q) red2[(q - 1) * 64 + o * 32 + p] = acc;
            __syncthreads();
            if (!q) {
                acc = add2(acc, red2[o * 32 + p]);
                acc = add2(acc, red2[64 + o * 32 + p]);
                acc = add2(acc, red2[128 + o * 32 + p]);
                float lo, hi;
                unpack2(acc, lo, hi);
                lo += bias; hi += bias;
                float* ob = out + o * (B * T);   // us then ws, each [B][T]
                ob[(2 * p) * T + t] = lo;
                ob[(2 * p + 1) * T + t] = hi;
                if (fin) {
                    for (int tau = t + 1; tau < T; ++tau) {
                        ob[(2 * p) * T + tau] = lo;
                        ob[(2 * p + 1) * T + tau] = hi;
                    }
                }
            }
            __syncthreads();
            if (tid == 0)   // "read of step t done" -> unblock workers to t+2
                publish(&g_flags[NWORK], fin ? 0xFFFFu : (2u * (uint)t + 7u));
            if (fin) break;
        }
    }

    // all 129 CTAs: final barrier, then reset globals for the next graph replay
    final_barrier();
    if (tid == 0) {
        asm volatile("st.relaxed.gpu.u32 [%0], %1;"
                     :: "l"(&g_flags[cta]), "r"(0u) : "memory");
        if (cta == 0)
            asm volatile("st.relaxed.gpu.u32 [%0], %1;"
                         :: "l"(&g_tconv), "r"(0x7FFFFFFFu) : "memory");
    }
}

extern "C" void kernel_launch(void* const* d_in, const int* in_sizes, int n_in,
                              void* d_out, int out_size) {
    (void)in_sizes; (void)n_in; (void)out_size;
    cudaFuncSetAttribute(fhn_kernel, cudaFuncAttributeMaxDynamicSharedMemorySize,
                         (int)SMEM_BYTES);
    fhn_kernel<<<NCTA, NT, SMEM_BYTES>>>(
        (const float*)d_in[0],   // u0
        (const float*)d_in[1],   // w0
        (const float*)d_in[2],   // K
        (const float*)d_in[3],   // W_in
        (const float*)d_in[4],   // b_in
        (const float*)d_in[5],   // W_ih0   (W_hh0 @6 unused)
        (const float*)d_in[7],   // b_ih0
        (const float*)d_in[8],   // b_hh0
        (const float*)d_in[9],   // W_ih1   (W_hh1 @10 unused)
        (const float*)d_in[11],  // b_ih1
        (const float*)d_in[12],  // b_hh1
        (const float*)d_in[13],  // W_u
        (const float*)d_in[14],  // b_u
        (const float*)d_in[15],  // W_w
        (const float*)d_in[16],  // b_w
        (float*)d_out);
}

// round 8
// speedup vs baseline: 1.9213x; 1.2224x over previous
#include <cuda_runtime.h>

typedef unsigned long long ull;
typedef unsigned int uint;

namespace {
constexpr int H = 512;
constexpr int B = 64;
constexpr int T = 1000;
constexpr int COLS = 4;
constexpr int NWORK = 128;
constexpr int NCTA = NWORK + 1;
constexpr int NT = 256;
// smem map (bytes): [0,48K) weights (24 rows x 512 f32, k-packed)
//                   [48K,176K) staged x (128KB); red aliases [152K,176K)
//                   [176K,+) mbars + flags
constexpr int WSM_BYTES = 24 * H * 4;          // 49152
constexpr int XSM_OFF = WSM_BYTES;             // 49152
constexpr int RED_OFF = XSM_OFF + 104 * 1024;  // aliases Xsm tail
constexpr int MB_OFF = XSM_OFF + 128 * 1024;   // 180224
constexpr unsigned SMEM_BYTES = MB_OFF + 512;  // 180736 <= 232448
}

__device__ float g_x[2][H * B];   // swizzled tiled layout, see G()
__device__ float g_h0[H * B];
__device__ uint g_flags[NCTA];    // workers: phase|sticky<<16; [128]: output phase
__device__ uint g_tconv = 0x7FFFFFFFu;
__device__ uint g_count = 0;
__device__ uint g_gen = 0;

__device__ __forceinline__ ull fma2(ull a, ull b, ull c) {
    ull d; asm("fma.rn.f32x2 %0, %1, %2, %3;" : "=l"(d) : "l"(a), "l"(b), "l"(c));
    return d;
}
__device__ __forceinline__ ull add2(ull a, ull b) {
    ull d; asm("add.rn.f32x2 %0, %1, %2;" : "=l"(d) : "l"(a), "l"(b));
    return d;
}
__device__ __forceinline__ void unpack2(ull v, float& lo, float& hi) {
    asm("mov.b64 {%0, %1}, %2;" : "=f"(lo), "=f"(hi) : "l"(v));
}
__device__ __forceinline__ float sigm(float x) {
    return __fdividef(1.0f, 1.0f + __expf(-x));
}
__device__ __forceinline__ float tanh_(float x) {
    return __fmaf_rn(2.0f, sigm(x + x), -1.0f);
}

// Bank swizzle of the batch index within its 8-group (conflict-free LDS.128).
__device__ __forceinline__ int sw16(int b) {
    return (b & 56) | ((b ^ (b >> 3)) & 7);
}
// Global float index of h[col c][batch b] in the tiled layout [k/4][swiz(b)][k%4].
__device__ __forceinline__ int G(int b, int c) {
    return ((c >> 2) << 8) + (sw16(b) << 2) + (c & 3);
}

__device__ __forceinline__ uint ldacq(const uint* a) {
    uint f;
    asm volatile("ld.acquire.gpu.u32 %0, [%1];" : "=r"(f) : "l"(a) : "memory");
    return f;
}
__device__ __forceinline__ void publish(uint* addr, uint v) {
    asm volatile("st.release.gpu.u32 [%0], %1;" :: "l"(addr), "r"(v) : "memory");
}

// Distributed flag barrier; all 4 (+1) loads issued per spin -> ~1 L2 round trip.
__device__ __forceinline__ void poll_flags(uint ph, uint* spub) {
    if (threadIdx.x < 32) {
        const uint* a = &g_flags[threadIdx.x];
        bool lane0 = (threadIdx.x == 0);
        uint f0, f1, f2, f3, f4;
        for (;;) {
            f0 = ldacq(a); f1 = ldacq(a + 32); f2 = ldacq(a + 64); f3 = ldacq(a + 96);
            f4 = lane0 ? ldacq(&g_flags[NWORK]) : 0xFFFFu;
            if ((f0 & 0xFFFFu) >= ph && (f1 & 0xFFFFu) >= ph &&
                (f2 & 0xFFFFu) >= ph && (f3 & 0xFFFFu) >= ph &&
                (f4 & 0xFFFFu) >= ph) break;
        }
        uint any = (f0 >> 16) | (f1 >> 16) | (f2 >> 16) | (f3 >> 16);
        uint r = __any_sync(0xFFFFFFFFu, any != 0u);
        if (lane0) *spub = r;
    }
}

__device__ __forceinline__ void final_barrier() {
    __syncthreads();
    if (threadIdx.x == 0) {
        uint snap, old;
        asm volatile("ld.acquire.gpu.u32 %0, [%1];" : "=r"(snap) : "l"(&g_gen) : "memory");
        asm volatile("atom.add.release.gpu.u32 %0, [%1], %2;"
                     : "=r"(old) : "l"(&g_count), "r"(1u) : "memory");
        if (old == NCTA - 1) {
            asm volatile("st.relaxed.gpu.u32 [%0], %1;" :: "l"(&g_count), "r"(0u) : "memory");
            asm volatile("st.release.gpu.u32 [%0], %1;" :: "l"(&g_gen), "r"(snap + 1u) : "memory");
        } else {
            uint g;
            do {
                asm volatile("ld.acquire.gpu.u32 %0, [%1];" : "=r"(g) : "l"(&g_gen) : "memory");
            } while (g == snap);
        }
    }
    __syncthreads();
}

__device__ __forceinline__ void mbar_init(uint mbar, uint cnt) {
    asm volatile("mbarrier.init.shared.b64 [%0], %1;" :: "r"(mbar), "r"(cnt) : "memory");
}
__device__ __forceinline__ void mbar_expect_tx(uint mbar, uint tx) {
    asm volatile("mbarrier.arrive.expect_tx.shared.b64 _, [%0], %1;"
                 :: "r"(mbar), "r"(tx) : "memory");
}
__device__ __forceinline__ void bulk_g2s(uint dst, const void* src, uint bytes, uint mbar) {
    asm volatile("cp.async.bulk.shared::cta.global.mbarrier::complete_tx::bytes "
                 "[%0], [%1], %2, [%3];" :: "r"(dst), "l"(src), "r"(bytes), "r"(mbar)
                 : "memory");
}
__device__ __forceinline__ void mbar_wait(uint mbar, uint parity) {
    asm volatile(
        "{\n\t.reg .pred P;\n\t"
        "LW%=: mbarrier.try_wait.parity.shared.b64 P, [%0], %1, 0x989680;\n\t"
        "@P bra LD%=;\n\t"
        "bra LW%=;\n\t"
        "LD%=: }\n\t" :: "r"(mbar), "r"(parity) : "memory");
}
__device__ __forceinline__ uint smem_u32(const void* p) {
    uint a;
    asm("{ .reg .u64 t; cvta.to.shared.u64 t, %1; cvt.u32.u64 %0, t; }" : "=r"(a) : "l"(p));
    return a;
}

__global__ __launch_bounds__(NT, 1) void fhn_kernel(
    const float* u0, const float* w0, const float* Kc,
    const float* W_in, const float* b_in,
    const float* W_ih0, const float* b_ih0, const float* b_hh0,
    const float* W_ih1, const float* b_ih1, const float* b_hh1,
    const float* W_u, const float* b_u, const float* W_w, const float* b_w,
    float* out)
{
    extern __shared__ char smem[];
    ulonglong2* Wsm = (ulonglong2*)smem;            // [24 rows][128 kb] (16B = 4 k)
    char* Xsm = smem + XSM_OFF;
    float* red = (float*)(smem + RED_OFF);          // [12][8][64]
    ull* mb = (ull*)(smem + MB_OFF);                // mb[0..7]
    uint* sflag = (uint*)(smem + MB_OFF + 64);
    uint* spub = sflag + 1;
    uint* stcv = sflag + 2;

    const int tid = threadIdx.x;
    const int cta = blockIdx.x;

    if (cta < NWORK) {
        // ========================= worker CTA =========================
        const int c0 = cta * COLS;
        const int gbase[3] = {0, 2 * H, 3 * H};   // i, g, o rows (f-gate dead)

        // weights: Wsm[row=l*12+g*4+cl][kb] <- W[(gbase[g]+c0+cl)*H + 4kb..+3]
        for (int i = tid; i < 24 * 128; i += NT) {
            int r = i >> 7, kb = i & 127;
            int l = r / 12, j = r % 12;
            int g = j >> 2, cl = j & 3;
            const float4* W = (const float4*)(l ? W_ih1 : W_ih0);
            ((float4*)Wsm)[i] = W[(gbase[g] + c0 + cl) * (H / 4) + kb];
        }
        if (tid == 0) {
            #pragma unroll
            for (int c = 0; c < 8; ++c) mbar_init(smem_u32(&mb[c]), 1);
            asm volatile("fence.proxy.async;" ::: "memory");
            *sflag = 0u;
        }
        // biases in regs for the epilogue thread (cl = tid>>6, b = tid&63)
        const int ecl = tid >> 6, eb = tid & 63;
        float bia[2][3];
        #pragma unroll
        for (int l = 0; l < 2; ++l) {
            const float* bih = l ? b_ih1 : b_ih0;
            const float* bhh = l ? b_hh1 : b_hh0;
            #pragma unroll
            for (int g = 0; g < 3; ++g) {
                int row = gbase[g] + c0 + ecl;
                bia[l][g] = bih[row] + bhh[row];
            }
        }
        {   // x0 = [u0,w0,K] @ W_in.T + b_in, written in tiled layout
            int c = c0 + ecl;
            float v = u0[eb] * W_in[c * 3 + 0] + w0[eb] * W_in[c * 3 + 1]
                    + Kc[eb] * W_in[c * 3 + 2] + b_in[c];
            g_x[0][G(eb, c)] = v;
        }

        uint sticky = 1u;
        __syncthreads();
        if (tid == 0) publish(&g_flags[cta], 1u | (sticky << 16));
        poll_flags(1u, spub);
        __syncthreads();

        const int lane = tid & 31;
        const int e = tid >> 5;          // k-eighth (warp)
        const int kb0 = e * 16;
        const int b0 = 2 * lane;         // this thread's two batches: b0, b0+1
        const int sofs = sw16(b0) * 16;  // b0 even -> b0+1 slot = sofs ^ 16
        const uint mbw = smem_u32(&mb[e]);
        const uint xsm0 = smem_u32(Xsm);

        int lyr = 0;
        int tdet = -1;
        bool done = false;
        #pragma unroll 1
        for (int t = 0; t < T && !done; ++t) {
            #pragma unroll
            for (int l = 0; l < 2; ++l) {
                const char* srcg = l ? (const char*)g_h0 : (const char*)g_x[t & 1];
                if (tid < 8) {
                    uint m = smem_u32(&mb[tid]);
                    mbar_expect_tx(m, 16384);
                    bulk_g2s(xsm0 + tid * 16384, srcg + tid * 16384, 16384, m);
                }
                float oldh = 0.f;
                if (l == 1)   // h1_{t-1} at this thread's epilogue slot (prefetch)
                    oldh = __ldcg(&g_x[t & 1][G(eb, c0 + ecl)]);

                mbar_wait(mbw, (uint)(lyr & 1));

                ull acc[12][2];
                #pragma unroll
                for (int j = 0; j < 12; ++j) { acc[j][0] = 0; acc[j][1] = 0; }
                const ulonglong2* wrow = Wsm + l * 12 * 128;
                #pragma unroll 2
                for (int kb = kb0; kb < kb0 + 16; ++kb) {
                    int ofs = kb * 1024 + sofs;
                    ulonglong2 xv0 = *(const ulonglong2*)(Xsm + ofs);        // b0, k..k+3
                    ulonglong2 xv1 = *(const ulonglong2*)(Xsm + (ofs ^ 16)); // b0+1
                    #pragma unroll
                    for (int j = 0; j < 12; ++j) {
                        ulonglong2 wv = wrow[j * 128 + kb];
                        acc[j][0] = fma2(xv0.x, wv.x, acc[j][0]);
                        acc[j][0] = fma2(xv0.y, wv.y, acc[j][0]);
                        acc[j][1] = fma2(xv1.x, wv.x, acc[j][1]);
                        acc[j][1] = fma2(xv1.y, wv.y, acc[j][1]);
                    }
                }
                __syncthreads();   // all Xsm reads done (red aliases Xsm tail)
                #pragma unroll
                for (int j = 0; j < 12; ++j) {
                    float a0, a1, a2, a3;
                    unpack2(acc[j][0], a0, a1);
                    unpack2(acc[j][1], a2, a3);
                    *(float2*)&red[j * 512 + e * 64 + b0] = make_float2(a0 + a1, a2 + a3);
                }
                __syncthreads();
                {   // epilogue: thread (ecl, eb) sums 8 partials x 3 gates
                    float s[3];
                    #pragma unroll
                    for (int g = 0; g < 3; ++g) {
                        const float* r = &red[(g * 4 + ecl) * 512 + eb];
                        float v = r[0];
                        #pragma unroll
                        for (int q = 1; q < 8; ++q) v += r[q * 64];
                        s[g] = v + bia[l][g];
                    }
                    float h = sigm(s[2]) * tanh_(sigm(s[0]) * tanh_(s[1]));
                    float* dst = l ? g_x[(t + 1) & 1] : g_h0;
                    dst[G(eb, c0 + ecl)] = h;
                    if (l == 1 && h != oldh) *sflag = 1u;
                }
                uint ph = (uint)(lyr + 2);
                __syncthreads();
                if (tid == 0) {
                    if (l == 1) { sticky = *sflag; *sflag = 0u; }
                    publish(&g_flags[cta], ph | (sticky << 16));
                }
                poll_flags(ph, spub);
                __syncthreads();
                if (l == 1 && *spub == 0u) { done = true; tdet = t; }
                lyr++;
            }
        }
        if (done && tid == 0) {
            asm volatile("st.relaxed.gpu.u32 [%0], %1;"
                         :: "l"(&g_tconv), "r"((uint)tdet) : "memory");
            publish(&g_flags[cta], 0xFFFFu);   // freeze
        }
    } else {
        // ========================= output CTA =========================
        float* Wof = (float*)smem;            // [2][512]
        float* red2 = (float*)(smem + 8192);  // [2][64]
        for (int i = tid; i < 2 * H; i += NT) {
            int o = i >> 9, c = i & (H - 1);
            Wof[i] = o ? W_w[c] : W_u[c];
        }
        const int b = tid & 63;
        const int o = (tid >> 6) & 1;
        const int q = tid >> 7;               // c-half
        const float bias = o ? b_w[0] : b_u[0];
        __syncthreads();
        if (tid == 0) publish(&g_flags[NWORK], 5u);

        const int swb = sw16(b) << 2;
        #pragma unroll 1
        for (int t = 0; t < T; ++t) {
            uint ph = 3u + 2u * (uint)t;      // layer-1 phase of step t
            poll_flags(ph, spub);
            if (tid == 0) {
                uint tc;
                asm volatile("ld.relaxed.gpu.u32 %0, [%1];" : "=r"(tc) : "l"(&g_tconv) : "memory");
                *stcv = tc;
            }
            __syncthreads();
            bool fin = ((uint)(t + 1) >= *stcv) || (t == T - 1);
            const float* hx = g_x[(t + 1) & 1];   // h1_t
            ull acc = 0;
            #pragma unroll 8
            for (int c = q * 256; c < q * 256 + 256; c += 4) {
                ulonglong2 hv = __ldcg((const ulonglong2*)(hx + ((c >> 2) << 8) + swb));
                ulonglong2 wv = *(const ulonglong2*)(Wof + o * H + c);
                acc = fma2(hv.x, wv.x, acc);
                acc = fma2(hv.y, wv.y, acc);
            }
            float lo, hi;
            unpack2(acc, lo, hi);
            float hs = lo + hi;
            if (q) red2[o * 64 + b] = hs;
            __syncthreads();
            if (!q) {
                hs += red2[o * 64 + b] + bias;
                float* ob = out + o * (B * T);    // us then ws, each [B][T]
                ob[b * T + t] = hs;
                if (fin) {
                    for (int tau = t + 1; tau < T; ++tau) ob[b * T + tau] = hs;
                }
            }
            __syncthreads();
            if (tid == 0)
                publish(&g_flags[NWORK], fin ? 0xFFFFu : (2u * (uint)t + 7u));
            if (fin) break;
        }
    }

    final_barrier();
    if (tid == 0) {
        asm volatile("st.relaxed.gpu.u32 [%0], %1;"
                     :: "l"(&g_flags[cta]), "r"(0u) : "memory");
        if (cta == 0)
            asm volatile("st.relaxed.gpu.u32 [%0], %1;"
                         :: "l"(&g_tconv), "r"(0x7FFFFFFFu) : "memory");
    }
}

extern "C" void kernel_launch(void* const* d_in, const int* in_sizes, int n_in,
                              void* d_out, int out_size) {
    (void)in_sizes; (void)n_in; (void)out_size;
    cudaFuncSetAttribute(fhn_kernel, cudaFuncAttributeMaxDynamicSharedMemorySize,
                         (int)SMEM_BYTES);
    fhn_kernel<<<NCTA, NT, SMEM_BYTES>>>(
        (const float*)d_in[0],   // u0
        (const float*)d_in[1],   // w0
        (const float*)d_in[2],   // K
        (const float*)d_in[3],   // W_in
        (const float*)d_in[4],   // b_in
        (const float*)d_in[5],   // W_ih0   (W_hh0 @6 unused)
        (const float*)d_in[7],   // b_ih0
        (const float*)d_in[8],   // b_hh0
        (const float*)d_in[9],   // W_ih1   (W_hh1 @10 unused)
        (const float*)d_in[11],  // b_ih1
        (const float*)d_in[12],  // b_hh1
        (const float*)d_in[13],  // W_u
        (const float*)d_in[14],  // b_u
        (const float*)d_in[15],  // W_w
        (const float*)d_in[16],  // b_w
        (float*)d_out);
}